// round 6
// baseline (speedup 1.0000x reference)
#include <cuda_runtime.h>
#include <cuda_bf16.h>
#include <cstdint>
#include <math.h>

// ---------------- problem constants ----------------
#define NTOK 4096
#define DDIM 2048
#define HDIM 1408
#define NE   16
#define NS   2
#define NSLOT (NE + NS)
#define TOPK 2
#define TM 128
#define TN 128
#define KC 32
#define MAXROWS (NTOK*TOPK + NE*TM + NTOK*NS)   // 18432
#define MAXTILESM (MAXROWS / TM)                // 144
#define SLOTSZ ((size_t)DDIM * HDIM)

// smem tile geometry: rows of 32 bf16 + 8 pad = 80 bytes (16B-aligned rows)
#define PITCH 80
#define TILEB (128 * PITCH)          // 10240 B
#define OFF_TOK 0
#define OFF_W   512
#define OFF_TILES 1024
#define AHOF(b) (OFF_TILES + (b)*4*TILEB)
#define ALOF(b) (AHOF(b) + TILEB)
#define BHOF(b) (AHOF(b) + 2*TILEB)
#define BLOF(b) (AHOF(b) + 3*TILEB)
#define SMEM_BYTES (OFF_TILES + 8*TILEB)   // 82944

// ---------------- device scratch ----------------
__device__ __align__(16) __nv_bfloat16 g_w1t_hi[NSLOT * SLOTSZ];  // [slot][H][D]
__device__ __align__(16) __nv_bfloat16 g_w1t_lo[NSLOT * SLOTSZ];
__device__ __align__(16) __nv_bfloat16 g_w2t_hi[NSLOT * SLOTSZ];  // [slot][D][H]
__device__ __align__(16) __nv_bfloat16 g_w2t_lo[NSLOT * SLOTSZ];
__device__ __align__(16) __nv_bfloat16 g_x_hi[(size_t)NTOK * DDIM];
__device__ __align__(16) __nv_bfloat16 g_x_lo[(size_t)NTOK * DDIM];
__device__ __align__(16) __nv_bfloat16 g_hidden_hi[(size_t)MAXROWS * HDIM];
__device__ __align__(16) __nv_bfloat16 g_hidden_lo[(size_t)MAXROWS * HDIM];
__device__ int   g_row_token[MAXROWS];
__device__ float g_row_w[MAXROWS];
__device__ int   g_tile_slot[MAXTILESM];
__device__ int   g_topk_i[NTOK * TOPK];
__device__ float g_topk_w[NTOK * TOPK];
__device__ int   g_counts[NE];
__device__ int   g_fill[NE];
__device__ int   g_offsets[NSLOT];
__device__ float g_psum[NE];
__device__ float g_lsum[NE];

// ---------------- helpers ----------------
__device__ __forceinline__ uint32_t smem_u32(const void* p) {
    uint32_t a;
    asm("{ .reg .u64 t; cvta.to.shared.u64 t, %1; cvt.u32.u64 %0, t; }"
        : "=r"(a) : "l"(p));
    return a;
}
__device__ __forceinline__ void ldsm4(uint32_t* r, uint32_t addr) {
    asm volatile("ldmatrix.sync.aligned.m8n8.x4.shared.b16 {%0,%1,%2,%3}, [%4];"
                 : "=r"(r[0]), "=r"(r[1]), "=r"(r[2]), "=r"(r[3]) : "r"(addr));
}
__device__ __forceinline__ void mma16816(float* d, const uint32_t* a, const uint32_t* b) {
    asm volatile("mma.sync.aligned.m16n8k16.row.col.f32.bf16.bf16.f32 "
                 "{%0,%1,%2,%3}, {%4,%5,%6,%7}, {%8,%9}, {%0,%1,%2,%3};"
                 : "+f"(d[0]), "+f"(d[1]), "+f"(d[2]), "+f"(d[3])
                 : "r"(a[0]), "r"(a[1]), "r"(a[2]), "r"(a[3]), "r"(b[0]), "r"(b[1]));
}
__device__ __forceinline__ uint32_t pk(__nv_bfloat16 a, __nv_bfloat16 b) {
    return (uint32_t)__bfloat16_as_ushort(a) | ((uint32_t)__bfloat16_as_ushort(b) << 16);
}
__device__ __forceinline__ void split_bf(float v, __nv_bfloat16& h, __nv_bfloat16& l) {
    h = __float2bfloat16_rn(v);
    l = __float2bfloat16_rn(v - __bfloat162float(h));
}

// ------- weight transpose+split: src [K][N] -> dst [N][K] hi/lo -------------
// PH=1: src = ew1/sw1 (K=DDIM,N=HDIM) -> g_w1t_*
// PH=2: src = ew2/sw2 (K=HDIM,N=DDIM) -> g_w2t_*
template <int PH>
__global__ void conv_w(const float* __restrict__ ew, const float* __restrict__ sw) {
    const int K = (PH == 1) ? DDIM : HDIM;
    const int N = (PH == 1) ? HDIM : DDIM;
    __nv_bfloat16* dst_hi = (PH == 1) ? g_w1t_hi : g_w2t_hi;
    __nv_bfloat16* dst_lo = (PH == 1) ? g_w1t_lo : g_w2t_lo;
    int slot = blockIdx.z;
    const float* src = (slot < NE) ? ew + (size_t)slot * K * N
                                   : sw + (size_t)(slot - NE) * K * N;
    __shared__ float t[32][33];
    int k0 = blockIdx.x * 32, n0 = blockIdx.y * 32;
    int tx = threadIdx.x, ty = threadIdx.y;   // 32, 8
#pragma unroll
    for (int i = 0; i < 4; i++)
        t[ty + i * 8][tx] = src[(size_t)(k0 + ty + i * 8) * N + n0 + tx];
    __syncthreads();
    __nv_bfloat16* dh = dst_hi + slot * SLOTSZ;
    __nv_bfloat16* dl = dst_lo + slot * SLOTSZ;
#pragma unroll
    for (int i = 0; i < 4; i++) {
        float v = t[tx][ty + i * 8];                 // src[k0+tx][n0+ty+i*8]
        __nv_bfloat16 h, l; split_bf(v, h, l);
        size_t o = (size_t)(n0 + ty + i * 8) * K + k0 + tx;
        dh[o] = h; dl[o] = l;
    }
}

// ---------------- x split (no transpose) ----------------
__global__ void conv_x(const float* __restrict__ x) {
    size_t i = ((size_t)blockIdx.x * blockDim.x + threadIdx.x) * 4;
    if (i >= (size_t)NTOK * DDIM) return;
    float4 v = *(const float4*)(x + i);
    __nv_bfloat16 h0, h1, h2, h3, l0, l1, l2, l3;
    split_bf(v.x, h0, l0); split_bf(v.y, h1, l1);
    split_bf(v.z, h2, l2); split_bf(v.w, h3, l3);
    *(uint2*)(g_x_hi + i) = make_uint2(pk(h0, h1), pk(h2, h3));
    *(uint2*)(g_x_lo + i) = make_uint2(pk(l0, l1), pk(l2, l3));
}

// ---------------- init ----------------
__global__ void init_kernel(float* __restrict__ out) {
    int idx = blockIdx.x * blockDim.x + threadIdx.x;
    int stride = gridDim.x * blockDim.x;
    for (size_t i = idx; i < (size_t)NTOK * DDIM; i += stride) out[i] = 0.0f;
    for (int i = idx; i < MAXROWS; i += stride) g_row_token[i] = -1;
    if (idx < NE) {
        g_counts[idx] = 0; g_fill[idx] = 0;
        g_psum[idx] = 0.0f; g_lsum[idx] = 0.0f;
    }
}

// ---------------- router ----------------
__global__ void router_kernel(const float* __restrict__ x,
                              const float* __restrict__ gw) {
    int t = blockIdx.x;
    int tid = threadIdx.x;
    float acc[NE];
#pragma unroll
    for (int e = 0; e < NE; e++) acc[e] = 0.0f;
    const float* xr = x + (size_t)t * DDIM;
    for (int d = tid; d < DDIM; d += 128) {
        float xv = xr[d];
        const float* g = gw + d * NE;
#pragma unroll
        for (int e = 0; e < NE; e++) acc[e] += xv * g[e];
    }
    __shared__ float red[128][NE + 1];
#pragma unroll
    for (int e = 0; e < NE; e++) red[tid][e] = acc[e];
    __syncthreads();
    for (int off = 64; off > 0; off >>= 1) {
        if (tid < off) {
#pragma unroll
            for (int e = 0; e < NE; e++) red[tid][e] += red[tid + off][e];
        }
        __syncthreads();
    }
    if (tid == 0) {
        float lg[NE], p[NE];
        float m = -1e30f;
#pragma unroll
        for (int e = 0; e < NE; e++) { lg[e] = red[0][e]; m = fmaxf(m, lg[e]); }
        float s = 0.0f;
#pragma unroll
        for (int e = 0; e < NE; e++) { p[e] = expf(lg[e] - m); s += p[e]; }
        float inv = 1.0f / s;
#pragma unroll
        for (int e = 0; e < NE; e++) p[e] *= inv;
        int i1 = 0;
#pragma unroll
        for (int e = 1; e < NE; e++) if (p[e] > p[i1]) i1 = e;
        int i2 = (i1 == 0) ? 1 : 0;
#pragma unroll
        for (int e = 0; e < NE; e++) if (e != i1 && p[e] > p[i2]) i2 = e;
        float wsum = p[i1] + p[i2];
        g_topk_i[t * 2 + 0] = i1;
        g_topk_i[t * 2 + 1] = i2;
        g_topk_w[t * 2 + 0] = p[i1] / wsum;
        g_topk_w[t * 2 + 1] = p[i2] / wsum;
        atomicAdd(&g_counts[i1], 1);
        atomicAdd(&g_counts[i2], 1);
#pragma unroll
        for (int e = 0; e < NE; e++) {
            atomicAdd(&g_psum[e], p[e]);
            atomicAdd(&g_lsum[e], lg[e]);
        }
    }
}

// ---------------- schedule ----------------
__global__ void schedule_kernel(float* __restrict__ out, long long out_size) {
    if (threadIdx.x != 0 || blockIdx.x != 0) return;
    int tile = 0;
    for (int slot = 0; slot < NSLOT; slot++) {
        int cnt = (slot < NE) ? g_counts[slot] : NTOK;
        g_offsets[slot] = tile * TM;
        int nt = (cnt + TM - 1) / TM;
        for (int i = 0; i < nt; i++) g_tile_slot[tile++] = slot;
    }
    for (; tile < MAXTILESM; tile++) g_tile_slot[tile] = -1;
    float aux = 0.0f;
    for (int e = 0; e < NE; e++)
        aux += (g_psum[e] * (1.0f / NTOK)) * (g_lsum[e] * (1.0f / NTOK));
    aux *= (float)NE;
    if (out_size > (long long)NTOK * DDIM) out[(size_t)NTOK * DDIM] = aux;
}

// ---------------- scatter ----------------
__global__ void scatter_kernel() {
    int i = blockIdx.x * blockDim.x + threadIdx.x;
    const int total = NTOK * TOPK + NTOK * NS;
    if (i >= total) return;
    if (i < NTOK * TOPK) {
        int e = g_topk_i[i];
        int pos = atomicAdd(&g_fill[e], 1);
        int row = g_offsets[e] + pos;
        g_row_token[row] = i >> 1;
        g_row_w[row] = g_topk_w[i];
    } else {
        int j = i - NTOK * TOPK;
        int s = j / NTOK, t = j % NTOK;
        int row = g_offsets[NE + s] + t;
        g_row_token[row] = t;
        g_row_w[row] = 1.0f;
    }
}

// ---------------- mma.sync grouped FFN GEMM, preconverted bf16, LDG+STS -----
// PHASE1: hidden = silu(gather(x) @ W1)   K=DDIM, N=HDIM
// PHASE2: out   += w_row * (hidden @ W2)  K=HDIM, N=DDIM (atomicAdd)
template <bool PHASE1>
__global__ __launch_bounds__(256, 2)
void ffn_mma(float* __restrict__ out) {
    extern __shared__ char smem[];
    const int bm = blockIdx.x, bn = blockIdx.y;
    const int slot = g_tile_slot[bm];
    if (slot < 0) return;
    const int KD = PHASE1 ? DDIM : HDIM;
    const int NC = KD / KC;
    const int row0 = bm * TM, n0 = bn * TN;
    const int tid = threadIdx.x, wid = tid >> 5, lane = tid & 31;
    int* s_tok = (int*)(smem + OFF_TOK);
    float* s_w = (float*)(smem + OFF_W);
    if (tid < TM) {
        s_tok[tid] = g_row_token[row0 + tid];
        s_w[tid]   = g_row_w[row0 + tid];
    }
    __syncthreads();

    // ---- source pointers (uint4 units; element offset baked in) ----
    const int lm  = tid >> 1;
    const int lkq = (tid & 1) * 16;       // elem offset
    const int lbn = tid & 127;
    const int lbk = (tid >> 7) * 16;
    const uint4 *pAh, *pAl, *pBh, *pBl;
    if (PHASE1) {
        int tok = s_tok[lm]; if (tok < 0) tok = 0;
        pAh = (const uint4*)(g_x_hi + (size_t)tok * DDIM + lkq);
        pAl = (const uint4*)(g_x_lo + (size_t)tok * DDIM + lkq);
        pBh = (const uint4*)(g_w1t_hi + slot * SLOTSZ + (size_t)(n0 + lbn) * DDIM + lbk);
        pBl = (const uint4*)(g_w1t_lo + slot * SLOTSZ + (size_t)(n0 + lbn) * DDIM + lbk);
    } else {
        pAh = (const uint4*)(g_hidden_hi + (size_t)(row0 + lm) * HDIM + lkq);
        pAl = (const uint4*)(g_hidden_lo + (size_t)(row0 + lm) * HDIM + lkq);
        pBh = (const uint4*)(g_w2t_hi + slot * SLOTSZ + (size_t)(n0 + lbn) * HDIM + lbk);
        pBl = (const uint4*)(g_w2t_lo + slot * SLOTSZ + (size_t)(n0 + lbn) * HDIM + lbk);
    }
    const int dA = lm * PITCH + lkq * 2;
    const int dB = lbn * PITCH + lbk * 2;

    const uint32_t sb = smem_u32(smem);
    const int warp_m = (wid >> 2) * 64;
    const int warp_n = (wid & 3) * 32;
    const int a_row = warp_m + (lane & 15);
    const int a_c8  = (lane >> 4) << 3;
    const int b_row = warp_n + (lane & 7) + ((lane >> 4) << 3);
    const int b_c8  = lane & 8;

    float acc[4][4][4];
#pragma unroll
    for (int i = 0; i < 4; i++)
#pragma unroll
        for (int j = 0; j < 4; j++)
#pragma unroll
            for (int k = 0; k < 4; k++) acc[i][j][k] = 0.0f;

    // -------- direct load of chunk 0 --------
    {
        *(uint4*)(smem + AHOF(0) + dA)      = pAh[0];
        *(uint4*)(smem + AHOF(0) + dA + 16) = pAh[1];
        *(uint4*)(smem + ALOF(0) + dA)      = pAl[0];
        *(uint4*)(smem + ALOF(0) + dA + 16) = pAl[1];
        *(uint4*)(smem + BHOF(0) + dB)      = pBh[0];
        *(uint4*)(smem + BHOF(0) + dB + 16) = pBh[1];
        *(uint4*)(smem + BLOF(0) + dB)      = pBl[0];
        *(uint4*)(smem + BLOF(0) + dB + 16) = pBl[1];
    }
    __syncthreads();

    // -------- main loop: register-staged prefetch of c+1, compute c --------
    for (int c = 0; c < NC; c++) {
        const int buf = c & 1;
        const bool have = (c + 1 < NC);
        const int j = (c + 1) * 4;          // uint4 index of next chunk

        uint4 sAh0, sAh1, sAl0, sAl1, sBh0, sBh1, sBl0, sBl1;
        if (have) {
            sAh0 = pAh[j]; sAh1 = pAh[j + 1];
            sAl0 = pAl[j]; sAl1 = pAl[j + 1];
            sBh0 = pBh[j]; sBh1 = pBh[j + 1];
            sBl0 = pBl[j]; sBl1 = pBl[j + 1];
        }

        // ---- compute on buffer `buf` ----
        {
            const uint32_t ahb = sb + AHOF(buf), alb = sb + ALOF(buf);
            const uint32_t bhb = sb + BHOF(buf), blb = sb + BLOF(buf);
#pragma unroll
            for (int ks = 0; ks < 2; ks++) {
                const int kk = ks * 16;
                const uint32_t baddr = (uint32_t)(b_row * PITCH + (kk + b_c8) * 2);
                const uint32_t aaddr = (uint32_t)(a_row * PITCH + (kk + a_c8) * 2);
                uint32_t bh0[4], bh1[4], bl0[4], bl1[4];
                ldsm4(bh0, bhb + baddr);
                ldsm4(bh1, bhb + baddr + 16 * PITCH);
                ldsm4(bl0, blb + baddr);
                ldsm4(bl1, blb + baddr + 16 * PITCH);
#pragma unroll
                for (int mi = 0; mi < 4; mi++) {
                    uint32_t af[4];
                    ldsm4(af, ahb + aaddr + mi * 16 * PITCH);
                    mma16816(acc[mi][0], af, bh0); mma16816(acc[mi][1], af, bh0 + 2);
                    mma16816(acc[mi][2], af, bh1); mma16816(acc[mi][3], af, bh1 + 2);
                    mma16816(acc[mi][0], af, bl0); mma16816(acc[mi][1], af, bl0 + 2);
                    mma16816(acc[mi][2], af, bl1); mma16816(acc[mi][3], af, bl1 + 2);
                    ldsm4(af, alb + aaddr + mi * 16 * PITCH);
                    mma16816(acc[mi][0], af, bh0); mma16816(acc[mi][1], af, bh0 + 2);
                    mma16816(acc[mi][2], af, bh1); mma16816(acc[mi][3], af, bh1 + 2);
                }
            }
        }

        // ---- STS staged chunk into other buffer ----
        if (have) {
            const int nb = (c + 1) & 1;
            *(uint4*)(smem + AHOF(nb) + dA)      = sAh0;
            *(uint4*)(smem + AHOF(nb) + dA + 16) = sAh1;
            *(uint4*)(smem + ALOF(nb) + dA)      = sAl0;
            *(uint4*)(smem + ALOF(nb) + dA + 16) = sAl1;
            *(uint4*)(smem + BHOF(nb) + dB)      = sBh0;
            *(uint4*)(smem + BHOF(nb) + dB + 16) = sBh1;
            *(uint4*)(smem + BLOF(nb) + dB)      = sBl0;
            *(uint4*)(smem + BLOF(nb) + dB + 16) = sBl1;
        }
        __syncthreads();
    }

    // -------- epilogue --------
    const int gid = lane >> 2, tig = lane & 3;
#pragma unroll
    for (int mi = 0; mi < 4; mi++) {
#pragma unroll
        for (int f = 0; f < 4; f++) {
            const int col = n0 + warp_n + f * 8 + tig * 2;
#pragma unroll
            for (int h = 0; h < 2; h++) {
                const int r = warp_m + mi * 16 + gid + h * 8;
                float v0 = acc[mi][f][2 * h];
                float v1 = acc[mi][f][2 * h + 1];
                if (PHASE1) {
                    v0 = v0 / (1.0f + __expf(-v0));
                    v1 = v1 / (1.0f + __expf(-v1));
                    __nv_bfloat16 h0, h1, l0, l1;
                    split_bf(v0, h0, l0); split_bf(v1, h1, l1);
                    size_t off = (size_t)(row0 + r) * HDIM + col;
                    *(uint32_t*)(g_hidden_hi + off) = pk(h0, h1);
                    *(uint32_t*)(g_hidden_lo + off) = pk(l0, l1);
                } else {
                    int tok = s_tok[r];
                    if (tok >= 0) {
                        float w = s_w[r];
                        float* op = out + (size_t)tok * DDIM + col;
                        atomicAdd(op,     w * v0);
                        atomicAdd(op + 1, w * v1);
                    }
                }
            }
        }
    }
}

// ---------------- launch ----------------
extern "C" void kernel_launch(void* const* d_in, const int* in_sizes, int n_in,
                              void* d_out, int out_size) {
    const float* x   = (const float*)d_in[0];
    const float* gw  = (const float*)d_in[1];
    const float* sw1 = (const float*)d_in[2];
    const float* sw2 = (const float*)d_in[3];
    const float* ew1 = (const float*)d_in[4];
    const float* ew2 = (const float*)d_in[5];
    float* out = (float*)d_out;

    cudaFuncSetAttribute(ffn_mma<true>,  cudaFuncAttributeMaxDynamicSharedMemorySize, SMEM_BYTES);
    cudaFuncSetAttribute(ffn_mma<false>, cudaFuncAttributeMaxDynamicSharedMemorySize, SMEM_BYTES);

    init_kernel<<<1024, 256>>>(out);
    router_kernel<<<NTOK, 128>>>(x, gw);
    schedule_kernel<<<1, 32>>>(out, (long long)out_size);
    scatter_kernel<<<(NTOK * (TOPK + NS) + 255) / 256, 256>>>();

    dim3 tb(32, 8);
    conv_w<1><<<dim3(DDIM / 32, HDIM / 32, NSLOT), tb>>>(ew1, sw1);
    conv_w<2><<<dim3(HDIM / 32, DDIM / 32, NSLOT), tb>>>(ew2, sw2);
    conv_x<<<(NTOK * DDIM / 4 + 255) / 256, 256>>>(x);

    dim3 g1(MAXTILESM, HDIM / TN);   // 144 x 11
    dim3 g2(MAXTILESM, DDIM / TN);   // 144 x 16
    ffn_mma<true ><<<g1, 256, SMEM_BYTES>>>(out);
    ffn_mma<false><<<g2, 256, SMEM_BYTES>>>(out);
}

// round 7
// speedup vs baseline: 1.2662x; 1.2662x over previous
#include <cuda_runtime.h>
#include <cuda_bf16.h>
#include <cstdint>
#include <math.h>

// ---------------- problem constants ----------------
#define NTOK 4096
#define DDIM 2048
#define HDIM 1408
#define NE   16
#define NS   2
#define NSLOT (NE + NS)
#define TOPK 2
#define TM 128
#define TN 128
#define KC 32
#define MAXROWS (NTOK*TOPK + NE*TM + NTOK*NS)   // 18432
#define MAXTILESM (MAXROWS / TM)                // 144
#define SLOTSZ ((size_t)DDIM * HDIM)
#define NBN1 (HDIM / TN)     // 11
#define NCH1 (DDIM / KC)     // 64
#define NBN2 (DDIM / TN)     // 16
#define NCH2 (HDIM / KC)     // 44
#define CHUNK_ELEM (2 * 128 * KC)   // 8192 elems (hi tile + lo tile)

// smem tile geometry: rows of 32 bf16 + 8 pad = 80 bytes (16B-aligned rows)
#define PITCH 80
#define TILEB (128 * PITCH)          // 10240 B
#define OFF_TOK 0
#define OFF_W   512
#define OFF_TILES 1024
#define AHOF(b) (OFF_TILES + (b)*4*TILEB)
#define ALOF(b) (AHOF(b) + TILEB)
#define BHOF(b) (AHOF(b) + 2*TILEB)
#define BLOF(b) (AHOF(b) + 3*TILEB)
#define SMEM_BYTES (OFF_TILES + 8*TILEB)   // 82944

// ---------------- device scratch (tiled layouts) ----------------
// w1t: [slot][bn(11)][c(64)][hi 128x32 | lo 128x32]
__device__ __align__(16) __nv_bfloat16 g_w1t[(size_t)NSLOT * NBN1 * NCH1 * CHUNK_ELEM];
// w2t: [slot][bn(16)][c(44)][hi|lo]
__device__ __align__(16) __nv_bfloat16 g_w2t[(size_t)NSLOT * NBN2 * NCH2 * CHUNK_ELEM];
// xc:  [tok][c(64)][hi 32 | lo 32]
__device__ __align__(16) __nv_bfloat16 g_xc[(size_t)NTOK * NCH1 * 64];
// hid: [rowblock(144)][c(44)][hi 128x32 | lo 128x32]
__device__ __align__(16) __nv_bfloat16 g_hid[(size_t)MAXTILESM * NCH2 * CHUNK_ELEM];
__device__ int   g_row_token[MAXROWS];
__device__ float g_row_w[MAXROWS];
__device__ int   g_tile_slot[MAXTILESM];
__device__ int   g_topk_i[NTOK * TOPK];
__device__ float g_topk_w[NTOK * TOPK];
__device__ int   g_counts[NE];
__device__ int   g_fill[NE];
__device__ int   g_offsets[NSLOT];
__device__ float g_psum[NE];
__device__ float g_lsum[NE];

// ---------------- helpers ----------------
__device__ __forceinline__ uint32_t smem_u32(const void* p) {
    uint32_t a;
    asm("{ .reg .u64 t; cvta.to.shared.u64 t, %1; cvt.u32.u64 %0, t; }"
        : "=r"(a) : "l"(p));
    return a;
}
__device__ __forceinline__ void ldsm4(uint32_t* r, uint32_t addr) {
    asm volatile("ldmatrix.sync.aligned.m8n8.x4.shared.b16 {%0,%1,%2,%3}, [%4];"
                 : "=r"(r[0]), "=r"(r[1]), "=r"(r[2]), "=r"(r[3]) : "r"(addr));
}
__device__ __forceinline__ void mma16816(float* d, const uint32_t* a, const uint32_t* b) {
    asm volatile("mma.sync.aligned.m16n8k16.row.col.f32.bf16.bf16.f32 "
                 "{%0,%1,%2,%3}, {%4,%5,%6,%7}, {%8,%9}, {%0,%1,%2,%3};"
                 : "+f"(d[0]), "+f"(d[1]), "+f"(d[2]), "+f"(d[3])
                 : "r"(a[0]), "r"(a[1]), "r"(a[2]), "r"(a[3]), "r"(b[0]), "r"(b[1]));
}
__device__ __forceinline__ uint32_t pk(__nv_bfloat16 a, __nv_bfloat16 b) {
    return (uint32_t)__bfloat16_as_ushort(a) | ((uint32_t)__bfloat16_as_ushort(b) << 16);
}
__device__ __forceinline__ void split_bf(float v, __nv_bfloat16& h, __nv_bfloat16& l) {
    h = __float2bfloat16_rn(v);
    l = __float2bfloat16_rn(v - __bfloat162float(h));
}

// ------- weight transpose+split into tiled layout ---------------------------
// PH=1: src = ew1/sw1 [K=DDIM][N=HDIM] -> g_w1t   PH=2: [K=HDIM][N=DDIM] -> g_w2t
template <int PH>
__global__ void conv_w(const float* __restrict__ ew, const float* __restrict__ sw) {
    const int K = (PH == 1) ? DDIM : HDIM;
    const int N = (PH == 1) ? HDIM : DDIM;
    const int NBN = (PH == 1) ? NBN1 : NBN2;
    const int NCH = (PH == 1) ? NCH1 : NCH2;
    __nv_bfloat16* dst = (PH == 1) ? g_w1t : g_w2t;
    int slot = blockIdx.z;
    const float* src = (slot < NE) ? ew + (size_t)slot * K * N
                                   : sw + (size_t)(slot - NE) * K * N;
    __shared__ float t[32][33];
    int k0 = blockIdx.x * 32, n0 = blockIdx.y * 32;
    int tx = threadIdx.x, ty = threadIdx.y;   // 32, 8
#pragma unroll
    for (int i = 0; i < 4; i++)
        t[ty + i * 8][tx] = src[(size_t)(k0 + ty + i * 8) * N + n0 + tx];
    __syncthreads();
    const int c = k0 >> 5;
#pragma unroll
    for (int i = 0; i < 4; i++) {
        int n = n0 + ty + i * 8;
        float v = t[tx][ty + i * 8];                 // src[k0+tx][n]
        __nv_bfloat16 h, l; split_bf(v, h, l);
        size_t base = ((size_t)(slot * NBN + (n >> 7)) * NCH + c) * CHUNK_ELEM
                      + (size_t)(n & 127) * KC + tx;
        dst[base] = h;
        dst[base + 128 * KC] = l;
    }
}

// ---------------- x split into chunk-interleaved layout ----------------
__global__ void conv_x(const float* __restrict__ x) {
    size_t i = ((size_t)blockIdx.x * blockDim.x + threadIdx.x) * 4;
    if (i >= (size_t)NTOK * DDIM) return;
    float4 v = *(const float4*)(x + i);
    __nv_bfloat16 h0, h1, h2, h3, l0, l1, l2, l3;
    split_bf(v.x, h0, l0); split_bf(v.y, h1, l1);
    split_bf(v.z, h2, l2); split_bf(v.w, h3, l3);
    int tok = (int)(i >> 11);
    int k = (int)(i & 2047);
    size_t base = ((size_t)tok * NCH1 + (k >> 5)) * 64 + (k & 31);
    *(uint2*)(g_xc + base)      = make_uint2(pk(h0, h1), pk(h2, h3));
    *(uint2*)(g_xc + base + 32) = make_uint2(pk(l0, l1), pk(l2, l3));
}

// ---------------- init ----------------
__global__ void init_kernel(float* __restrict__ out) {
    int idx = blockIdx.x * blockDim.x + threadIdx.x;
    int stride = gridDim.x * blockDim.x;
    for (size_t i = idx; i < (size_t)NTOK * DDIM; i += stride) out[i] = 0.0f;
    for (int i = idx; i < MAXROWS; i += stride) g_row_token[i] = -1;
    if (idx < NE) {
        g_counts[idx] = 0; g_fill[idx] = 0;
        g_psum[idx] = 0.0f; g_lsum[idx] = 0.0f;
    }
}

// ---------------- router ----------------
__global__ void router_kernel(const float* __restrict__ x,
                              const float* __restrict__ gw) {
    int t = blockIdx.x;
    int tid = threadIdx.x;
    float acc[NE];
#pragma unroll
    for (int e = 0; e < NE; e++) acc[e] = 0.0f;
    const float* xr = x + (size_t)t * DDIM;
    for (int d = tid; d < DDIM; d += 128) {
        float xv = xr[d];
        const float* g = gw + d * NE;
#pragma unroll
        for (int e = 0; e < NE; e++) acc[e] += xv * g[e];
    }
    __shared__ float red[128][NE + 1];
#pragma unroll
    for (int e = 0; e < NE; e++) red[tid][e] = acc[e];
    __syncthreads();
    for (int off = 64; off > 0; off >>= 1) {
        if (tid < off) {
#pragma unroll
            for (int e = 0; e < NE; e++) red[tid][e] += red[tid + off][e];
        }
        __syncthreads();
    }
    if (tid == 0) {
        float lg[NE], p[NE];
        float m = -1e30f;
#pragma unroll
        for (int e = 0; e < NE; e++) { lg[e] = red[0][e]; m = fmaxf(m, lg[e]); }
        float s = 0.0f;
#pragma unroll
        for (int e = 0; e < NE; e++) { p[e] = expf(lg[e] - m); s += p[e]; }
        float inv = 1.0f / s;
#pragma unroll
        for (int e = 0; e < NE; e++) p[e] *= inv;
        int i1 = 0;
#pragma unroll
        for (int e = 1; e < NE; e++) if (p[e] > p[i1]) i1 = e;
        int i2 = (i1 == 0) ? 1 : 0;
#pragma unroll
        for (int e = 0; e < NE; e++) if (e != i1 && p[e] > p[i2]) i2 = e;
        float wsum = p[i1] + p[i2];
        g_topk_i[t * 2 + 0] = i1;
        g_topk_i[t * 2 + 1] = i2;
        g_topk_w[t * 2 + 0] = p[i1] / wsum;
        g_topk_w[t * 2 + 1] = p[i2] / wsum;
        atomicAdd(&g_counts[i1], 1);
        atomicAdd(&g_counts[i2], 1);
#pragma unroll
        for (int e = 0; e < NE; e++) {
            atomicAdd(&g_psum[e], p[e]);
            atomicAdd(&g_lsum[e], lg[e]);
        }
    }
}

// ---------------- schedule ----------------
__global__ void schedule_kernel(float* __restrict__ out, long long out_size) {
    if (threadIdx.x != 0 || blockIdx.x != 0) return;
    int tile = 0;
    for (int slot = 0; slot < NSLOT; slot++) {
        int cnt = (slot < NE) ? g_counts[slot] : NTOK;
        g_offsets[slot] = tile * TM;
        int nt = (cnt + TM - 1) / TM;
        for (int i = 0; i < nt; i++) g_tile_slot[tile++] = slot;
    }
    for (; tile < MAXTILESM; tile++) g_tile_slot[tile] = -1;
    float aux = 0.0f;
    for (int e = 0; e < NE; e++)
        aux += (g_psum[e] * (1.0f / NTOK)) * (g_lsum[e] * (1.0f / NTOK));
    aux *= (float)NE;
    if (out_size > (long long)NTOK * DDIM) out[(size_t)NTOK * DDIM] = aux;
}

// ---------------- scatter ----------------
__global__ void scatter_kernel() {
    int i = blockIdx.x * blockDim.x + threadIdx.x;
    const int total = NTOK * TOPK + NTOK * NS;
    if (i >= total) return;
    if (i < NTOK * TOPK) {
        int e = g_topk_i[i];
        int pos = atomicAdd(&g_fill[e], 1);
        int row = g_offsets[e] + pos;
        g_row_token[row] = i >> 1;
        g_row_w[row] = g_topk_w[i];
    } else {
        int j = i - NTOK * TOPK;
        int s = j / NTOK, t = j % NTOK;
        int row = g_offsets[NE + s] + t;
        g_row_token[row] = t;
        g_row_w[row] = 1.0f;
    }
}

// ----- mma.sync grouped FFN GEMM; tiled pre-split bf16; coalesced feed ------
// PHASE1: hidden = silu(gather(x) @ W1)   K=DDIM, N=HDIM -> g_hid (tiled)
// PHASE2: out   += w_row * (hidden @ W2)  K=HDIM, N=DDIM (atomicAdd)
template <bool PHASE1>
__global__ __launch_bounds__(256, 2)
void ffn_mma(float* __restrict__ out) {
    extern __shared__ char smem[];
    const int bm = blockIdx.x, bn = blockIdx.y;
    const int slot = g_tile_slot[bm];
    if (slot < 0) return;
    const int NC = PHASE1 ? NCH1 : NCH2;
    const int row0 = bm * TM, n0 = bn * TN;
    const int tid = threadIdx.x, wid = tid >> 5, lane = tid & 31;
    int* s_tok = (int*)(smem + OFF_TOK);
    float* s_w = (float*)(smem + OFF_W);
    if (tid < TM) {
        s_tok[tid] = g_row_token[row0 + tid];
        s_w[tid]   = g_row_w[row0 + tid];
    }
    __syncthreads();

    // ---- tiled-block loader offsets (unit u = tid + i*256 of 16B) ----
    int tDst[4], tLo[4];
#pragma unroll
    for (int i = 0; i < 4; i++) {
        int u = tid + i * 256;
        int rem = u & 511;
        tDst[i] = (rem >> 2) * PITCH + (rem & 3) * 16;
        tLo[i]  = u >> 9;                      // 0 = hi half, 1 = lo half
    }

    // ---- source pointers ----
    const uint4* srcB;
    if (PHASE1)
        srcB = (const uint4*)g_w1t + (size_t)(slot * NBN1 + bn) * NCH1 * 1024;
    else
        srcB = (const uint4*)g_w2t + (size_t)(slot * NBN2 + bn) * NCH2 * 1024;
    const uint4* srcA2 = 0;       // phase2 tiled A
    const char*  srcA1 = 0;       // phase1 per-token A
    int sub = tid & 1;
    if (PHASE1) {
        int lm = tid >> 1;
        int tok = s_tok[lm]; if (tok < 0) tok = 0;
        srcA1 = (const char*)(g_xc + (size_t)tok * NCH1 * 64);
    } else {
        srcA2 = (const uint4*)g_hid + (size_t)bm * NCH2 * 1024;
    }
    const int dA1 = (tid >> 1) * PITCH + sub * 32;   // phase1 A smem dest

    const uint32_t sb = smem_u32(smem);
    const int warp_m = (wid >> 2) * 64;
    const int warp_n = (wid & 3) * 32;
    const int a_row = warp_m + (lane & 15);
    const int a_c8  = (lane >> 4) << 3;
    const int b_row = warp_n + (lane & 7) + ((lane >> 4) << 3);
    const int b_c8  = lane & 8;

    float acc[4][4][4];
#pragma unroll
    for (int i = 0; i < 4; i++)
#pragma unroll
        for (int j = 0; j < 4; j++)
#pragma unroll
            for (int k = 0; k < 4; k++) acc[i][j][k] = 0.0f;

    // -------- direct load of chunk 0 --------
    {
        if (PHASE1) {
            const uint4* p = (const uint4*)srcA1;    // chunk 0
            *(uint4*)(smem + AHOF(0) + dA1)      = p[sub * 2];
            *(uint4*)(smem + AHOF(0) + dA1 + 16) = p[sub * 2 + 1];
            *(uint4*)(smem + ALOF(0) + dA1)      = p[4 + sub * 2];
            *(uint4*)(smem + ALOF(0) + dA1 + 16) = p[4 + sub * 2 + 1];
        } else {
#pragma unroll
            for (int i = 0; i < 4; i++)
                *(uint4*)(smem + (tLo[i] ? ALOF(0) : AHOF(0)) + tDst[i]) = srcA2[tid + i * 256];
        }
#pragma unroll
        for (int i = 0; i < 4; i++)
            *(uint4*)(smem + (tLo[i] ? BLOF(0) : BHOF(0)) + tDst[i]) = srcB[tid + i * 256];
    }
    __syncthreads();

    // -------- main loop --------
    for (int c = 0; c < NC; c++) {
        const int buf = c & 1;
        const bool have = (c + 1 < NC);

        uint4 sA[4], sB[4];
        if (have) {
            if (PHASE1) {
                const uint4* p = (const uint4*)(srcA1 + (c + 1) * 128);
                sA[0] = p[sub * 2];     sA[1] = p[sub * 2 + 1];
                sA[2] = p[4 + sub * 2]; sA[3] = p[4 + sub * 2 + 1];
            } else {
                const uint4* p = srcA2 + (size_t)(c + 1) * 1024;
#pragma unroll
                for (int i = 0; i < 4; i++) sA[i] = p[tid + i * 256];
            }
            const uint4* q = srcB + (size_t)(c + 1) * 1024;
#pragma unroll
            for (int i = 0; i < 4; i++) sB[i] = q[tid + i * 256];
        }

        // ---- compute on buffer `buf` ----
        {
            const uint32_t ahb = sb + AHOF(buf), alb = sb + ALOF(buf);
            const uint32_t bhb = sb + BHOF(buf), blb = sb + BLOF(buf);
#pragma unroll
            for (int ks = 0; ks < 2; ks++) {
                const int kk = ks * 16;
                const uint32_t baddr = (uint32_t)(b_row * PITCH + (kk + b_c8) * 2);
                const uint32_t aaddr = (uint32_t)(a_row * PITCH + (kk + a_c8) * 2);
                uint32_t bh0[4], bh1[4], bl0[4], bl1[4];
                ldsm4(bh0, bhb + baddr);
                ldsm4(bh1, bhb + baddr + 16 * PITCH);
                ldsm4(bl0, blb + baddr);
                ldsm4(bl1, blb + baddr + 16 * PITCH);
#pragma unroll
                for (int mi = 0; mi < 4; mi++) {
                    uint32_t af[4];
                    ldsm4(af, ahb + aaddr + mi * 16 * PITCH);
                    mma16816(acc[mi][0], af, bh0); mma16816(acc[mi][1], af, bh0 + 2);
                    mma16816(acc[mi][2], af, bh1); mma16816(acc[mi][3], af, bh1 + 2);
                    mma16816(acc[mi][0], af, bl0); mma16816(acc[mi][1], af, bl0 + 2);
                    mma16816(acc[mi][2], af, bl1); mma16816(acc[mi][3], af, bl1 + 2);
                    ldsm4(af, alb + aaddr + mi * 16 * PITCH);
                    mma16816(acc[mi][0], af, bh0); mma16816(acc[mi][1], af, bh0 + 2);
                    mma16816(acc[mi][2], af, bh1); mma16816(acc[mi][3], af, bh1 + 2);
                }
            }
        }

        // ---- STS staged chunk into other buffer ----
        if (have) {
            const int nb = (c + 1) & 1;
            if (PHASE1) {
                *(uint4*)(smem + AHOF(nb) + dA1)      = sA[0];
                *(uint4*)(smem + AHOF(nb) + dA1 + 16) = sA[1];
                *(uint4*)(smem + ALOF(nb) + dA1)      = sA[2];
                *(uint4*)(smem + ALOF(nb) + dA1 + 16) = sA[3];
            } else {
#pragma unroll
                for (int i = 0; i < 4; i++)
                    *(uint4*)(smem + (tLo[i] ? ALOF(nb) : AHOF(nb)) + tDst[i]) = sA[i];
            }
#pragma unroll
            for (int i = 0; i < 4; i++)
                *(uint4*)(smem + (tLo[i] ? BLOF(nb) : BHOF(nb)) + tDst[i]) = sB[i];
        }
        __syncthreads();
    }

    // -------- epilogue --------
    const int gid = lane >> 2, tig = lane & 3;
#pragma unroll
    for (int mi = 0; mi < 4; mi++) {
#pragma unroll
        for (int f = 0; f < 4; f++) {
            const int col = n0 + warp_n + f * 8 + tig * 2;
#pragma unroll
            for (int h = 0; h < 2; h++) {
                const int r = warp_m + mi * 16 + gid + h * 8;
                float v0 = acc[mi][f][2 * h];
                float v1 = acc[mi][f][2 * h + 1];
                if (PHASE1) {
                    v0 = v0 / (1.0f + __expf(-v0));
                    v1 = v1 / (1.0f + __expf(-v1));
                    __nv_bfloat16 h0, h1, l0, l1;
                    split_bf(v0, h0, l0); split_bf(v1, h1, l1);
                    // hidden tiled: [bm][col>>5][hi|lo][r][col&31]
                    size_t base = ((size_t)bm * NCH2 + (col >> 5)) * CHUNK_ELEM
                                  + (size_t)r * KC + (col & 31);
                    *(uint32_t*)(g_hid + base)            = pk(h0, h1);
                    *(uint32_t*)(g_hid + base + 128 * KC) = pk(l0, l1);
                } else {
                    int tok = s_tok[r];
                    if (tok >= 0) {
                        float w = s_w[r];
                        float* op = out + (size_t)tok * DDIM + col;
                        atomicAdd(op,     w * v0);
                        atomicAdd(op + 1, w * v1);
                    }
                }
            }
        }
    }
}

// ---------------- launch ----------------
extern "C" void kernel_launch(void* const* d_in, const int* in_sizes, int n_in,
                              void* d_out, int out_size) {
    const float* x   = (const float*)d_in[0];
    const float* gw  = (const float*)d_in[1];
    const float* sw1 = (const float*)d_in[2];
    const float* sw2 = (const float*)d_in[3];
    const float* ew1 = (const float*)d_in[4];
    const float* ew2 = (const float*)d_in[5];
    float* out = (float*)d_out;

    cudaFuncSetAttribute(ffn_mma<true>,  cudaFuncAttributeMaxDynamicSharedMemorySize, SMEM_BYTES);
    cudaFuncSetAttribute(ffn_mma<false>, cudaFuncAttributeMaxDynamicSharedMemorySize, SMEM_BYTES);

    init_kernel<<<1024, 256>>>(out);
    router_kernel<<<NTOK, 128>>>(x, gw);
    schedule_kernel<<<1, 32>>>(out, (long long)out_size);
    scatter_kernel<<<(NTOK * (TOPK + NS) + 255) / 256, 256>>>();

    dim3 tb(32, 8);
    conv_w<1><<<dim3(DDIM / 32, HDIM / 32, NSLOT), tb>>>(ew1, sw1);
    conv_w<2><<<dim3(HDIM / 32, DDIM / 32, NSLOT), tb>>>(ew2, sw2);
    conv_x<<<(NTOK * DDIM / 4 + 255) / 256, 256>>>(x);

    dim3 g1(MAXTILESM, HDIM / TN);   // 144 x 11
    dim3 g2(MAXTILESM, DDIM / TN);   // 144 x 16
    ffn_mma<true ><<<g1, 256, SMEM_BYTES>>>(out);
    ffn_mma<false><<<g2, 256, SMEM_BYTES>>>(out);
}